// round 14
// baseline (speedup 1.0000x reference)
#include <cuda_runtime.h>
#include <cuda_bf16.h>
#include <cuda_fp16.h>

// Problem constants (B=8, N=256, H=128)
#define BB 8
#define NN 256
#define HH 128
#define ROWS (BB * NN)        // 2048
#define TIF 16                // i-rows per fused CTA

typedef unsigned long long ull;
typedef unsigned int uint;

// Scratch: g_P = 0.5*(node@We1a + be1) f32 ; g_Qh = 0.5*(node@We1b) dup half2
__device__ float g_P[ROWS * HH];
__device__ uint  g_Qh[ROWS * HH];

// ---------------- packed f32x2 / fp16 helpers ----------------
__device__ __forceinline__ ull fma2(ull a, ull b, ull c) {
    ull d; asm("fma.rn.f32x2 %0, %1, %2, %3;" : "=l"(d) : "l"(a), "l"(b), "l"(c)); return d;
}
__device__ __forceinline__ ull add2(ull a, ull b) {
    ull d; asm("add.rn.f32x2 %0, %1, %2;" : "=l"(d) : "l"(a), "l"(b)); return d;
}
__device__ __forceinline__ ull mul2(ull a, ull b) {
    ull d; asm("mul.rn.f32x2 %0, %1, %2;" : "=l"(d) : "l"(a), "l"(b)); return d;
}
__device__ __forceinline__ ull pack2(float lo, float hi) {
    ull d; asm("mov.b64 %0, {%1, %2};" : "=l"(d) : "f"(lo), "f"(hi)); return d;
}
__device__ __forceinline__ void unpack2(ull v, float& lo, float& hi) {
    asm("mov.b64 {%0, %1}, %2;" : "=f"(lo), "=f"(hi) : "l"(v));
}
__device__ __forceinline__ float sqrtfast(float x) {
    float y; asm("sqrt.approx.f32 %0, %1;" : "=f"(y) : "f"(x)); return y;
}
__device__ __forceinline__ float fast_sigmoid(float x) {
    float e; asm("ex2.approx.f32 %0, %1;" : "=f"(e) : "f"(-1.4426950408889634f * x));
    float r; asm("rcp.approx.f32 %0, %1;" : "=f"(r) : "f"(1.0f + e));
    return r;
}
__device__ __forceinline__ __half2 tanh2h(__half2 h) {
    unsigned u = *reinterpret_cast<unsigned*>(&h);
    asm("tanh.approx.f16x2 %0, %0;" : "+r"(u));
    return *reinterpret_cast<__half2*>(&u);
}
__device__ __forceinline__ __half2 u2h2(uint u) { return *reinterpret_cast<__half2*>(&u); }
__device__ __forceinline__ uint h2u(__half2 h) { return *reinterpret_cast<uint*>(&h); }
__device__ __forceinline__ uint smem_u32(const void* p) {
    uint a; asm("{ .reg .u64 t; cvta.to.shared.u64 t, %1; cvt.u32.u64 %0, t; }"
                : "=r"(a) : "l"(p));
    return a;
}
__device__ __forceinline__ void cp_async16(uint dst, const void* src) {
    asm volatile("cp.async.cg.shared.global [%0], [%1], 16;" :: "r"(dst), "l"(src));
}
#define CP_COMMIT() asm volatile("cp.async.commit_group;" ::: "memory")
#define CP_WAIT(n)  asm volatile("cp.async.wait_group %0;" :: "n"(n) : "memory")

// ---- stage-B GEMV helpers (register-LDG path, unchanged from R12) ----
__device__ __forceinline__ void loadw16(float (&buf)[16], const float* Wk, int c) {
#pragma unroll
    for (int e = 0; e < 16; e++) buf[e] = Wk[(c * 16 + e) * HH];
}
__device__ __forceinline__ void gemv_chunk(const float (&w)[16], const ull* src,
                                           int c, int g, ull (&acc)[2]) {
#pragma unroll
    for (int e = 0; e < 16; e++) {
        ull w2 = pack2(w[e], w[e]);
#pragma unroll
        for (int pp = 0; pp < 2; pp++)
            acc[pp] = fma2(src[(c * 16 + e) * 8 + 2 * g + pp], w2, acc[pp]);
    }
}

// ---------------------------------------------------------------------------
// Kernel 1: unchanged from R13.
// ---------------------------------------------------------------------------
#define PQ_SMEM (131072 + 8192)
__global__ __launch_bounds__(512, 1)
void k_pq(const float* __restrict__ node,
          const float* __restrict__ We1,
          const float* __restrict__ be1) {
    extern __shared__ __align__(16) char smem_pq[];
    float* wsm = (float*)smem_pq;
    ull*   xs2 = (ull*)(smem_pq + 131072);

    int row0 = blockIdx.x * 16;
    int tid = threadIdx.x;
    int k = tid & 127;
    int half = (tid >> 7) & 1;
    int rg = tid >> 8;

    {
        const float4* wsrc = (const float4*)We1;
        float4* wdst = (float4*)wsm;
#pragma unroll
        for (int i = 0; i < 16; i++) wdst[tid + i * 512] = wsrc[tid + i * 512];
    }
    {
#pragma unroll
        for (int t = 0; t < 2; t++) {
            int idx = tid + t * 512;
            int e = idx & 127, p = idx >> 7;
            xs2[e * 8 + p] = pack2(node[(row0 + 2 * p) * HH + e],
                                   node[(row0 + 2 * p + 1) * HH + e]);
        }
    }
    __syncthreads();

    const float* W = wsm + half * (HH * HH) + k;
    float bv = half ? 0.0f : be1[k];
    ull acc2[4];
#pragma unroll
    for (int p = 0; p < 4; p++) acc2[p] = pack2(bv, bv);

#pragma unroll 8
    for (int e = 0; e < HH; e++) {
        float w = W[e * HH];
        ull w2 = pack2(w, w);
        ulonglong2 xa = *(const ulonglong2*)&xs2[e * 8 + rg * 4];
        ulonglong2 xb = *(const ulonglong2*)&xs2[e * 8 + rg * 4 + 2];
        acc2[0] = fma2(xa.x, w2, acc2[0]);
        acc2[1] = fma2(xa.y, w2, acc2[1]);
        acc2[2] = fma2(xb.x, w2, acc2[2]);
        acc2[3] = fma2(xb.y, w2, acc2[3]);
    }

    ull hc = pack2(0.5f, 0.5f);
    if (half == 0) {
#pragma unroll
        for (int p = 0; p < 4; p++) {
            float lo, hi; unpack2(mul2(acc2[p], hc), lo, hi);
            int pr = rg * 4 + p;
            g_P[(row0 + 2 * pr) * HH + k] = lo;
            g_P[(row0 + 2 * pr + 1) * HH + k] = hi;
        }
    } else {
#pragma unroll
        for (int p = 0; p < 4; p++) {
            float lo, hi; unpack2(mul2(acc2[p], hc), lo, hi);
            int pr = rg * 4 + p;
            g_Qh[(row0 + 2 * pr) * HH + k] = h2u(__floats2half2_rn(lo, lo));
            g_Qh[(row0 + 2 * pr + 1) * HH + k] = h2u(__floats2half2_rn(hi, hi));
        }
    }
}

// ---------------------------------------------------------------------------
// Fused kernel. Edge unchanged from R13. Tail weights for stages A & C are
// cp.async-prefetched into smem (We2 during edge, Wn2 during stage A/B),
// read via conflict-free LDS with zero global latency. Wn1 keeps the
// register-LDG double buffer. XA2/SU2/Wn2-buffer alias dead QSM space.
// ---------------------------------------------------------------------------
#define QSM_OFF  0          // uint[256][128] dup-half2   131072 (dead after edge)
#define XA2_OFF  0          //   alias: ull[256][8]       16384
#define SU2_OFF  16384      //   alias: ull[128][8]       8192
#define WC_OFF   24576      //   alias: float[128][128]   65536 (Wn2)
#define BSM_OFF  131072     // float[16][128]             8192
#define DSM_OFF  139264     // __half2[8][256]            8192
#define MSM_OFF  147456     // __half2[256]               1024
#define S2_OFF   148480     // ull[2][128][8]             16384
#define WA_OFF   164864     // float[128][128]            65536 (We2)
#define MROW_OFF 230400     // float[16]
#define CNT_OFF  230464     // float
#define FU_SMEM  230528

__global__ __launch_bounds__(512, 1)
void k_fused(const float* __restrict__ node,
             const float* __restrict__ pos,
             const float* __restrict__ mask,
             const float* __restrict__ We1,
             const float* __restrict__ We2,
             const float* __restrict__ be2,
             const float* __restrict__ Wn1,
             const float* __restrict__ bn1,
             const float* __restrict__ Wn2,
             const float* __restrict__ bn2,
             float* __restrict__ out) {
    extern __shared__ __align__(16) char smem[];
    uint*    QSMh = (uint*)(smem + QSM_OFF);
    ull*     XA2  = (ull*)(smem + XA2_OFF);      // aliases QSM (used post-edge)
    ull*     SU2  = (ull*)(smem + SU2_OFF);      // aliases QSM
    float*   WC   = (float*)(smem + WC_OFF);     // aliases QSM (Wn2)
    float*   BSM  = (float*)(smem + BSM_OFF);
    __half2* DSMH = (__half2*)(smem + DSM_OFF);
    __half2* MSMH = (__half2*)(smem + MSM_OFF);
    ull*     S2   = (ull*)(smem + S2_OFF);
    float*   WA   = (float*)(smem + WA_OFF);     // We2
    float*   MROW = (float*)(smem + MROW_OFF);
    float*   CNT  = (float*)(smem + CNT_OFF);

    int i0 = blockIdx.x * TIF;
    int b  = blockIdx.y;
    int tid = threadIdx.x;
    int row0 = b * NN + i0;

    // ---------------- prologue ----------------
    {   // prefetch We2 (64 KB) via cp.async — completes during the edge phase
        uint wa_s = smem_u32(WA) + tid * 16;
        const char* wsrc = (const char*)We2 + tid * 16;
#pragma unroll
        for (int i = 0; i < 8; i++)
            cp_async16(wa_s + i * 8192, wsrc + i * 8192);
        CP_COMMIT();                              // group G0
    }
    {
        const float4* qsrc = (const float4*)&g_Qh[b * NN * HH];
#pragma unroll
        for (int i = 0; i < 16; i++)
            ((float4*)QSMh)[tid + i * 512] = qsrc[tid + i * 512];
        const float4* bsrc = (const float4*)&g_P[row0 * HH];
        ((float4*)BSM)[tid] = bsrc[tid];
    }
    // X values carried in registers through the edge phase (XA2 aliases QSM)
    float xv[4];
    int xe, xp;
    {
        xe = tid & 127; xp = tid >> 7;            // entries (xe, xp) and (xe, xp+... )
#pragma unroll
        for (int t = 0; t < 2; t++) {
            int idx = tid + t * 512;
            int e = idx & 127, p = idx >> 7;
            xv[2 * t]     = node[(row0 + 2 * p) * HH + e];
            xv[2 * t + 1] = node[(row0 + 2 * p + 1) * HH + e];
        }
    }
    {   // dist row-pair tile: 8 ip x 256 j, fp16
#pragma unroll
        for (int t = 0; t < 4; t++) {
            int idx = tid + t * 512;
            int ip = idx >> 8, jl = idx & 255;
            const float* p0 = &pos[(row0 + 2 * ip) * 3];
            const float* p1 = &pos[(row0 + 2 * ip + 1) * 3];
            const float* pj = &pos[(b * NN + jl) * 3];
            float jx = pj[0], jy = pj[1], jz = pj[2];
            float dx0 = p0[0] - jx, dy0 = p0[1] - jy, dz0 = p0[2] - jz;
            float dx1 = p1[0] - jx, dy1 = p1[1] - jy, dz1 = p1[2] - jz;
            float s0 = fmaf(dx0, dx0, fmaf(dy0, dy0, dz0 * dz0));
            float s1 = fmaf(dx1, dx1, fmaf(dy1, dy1, dz1 * dz1));
            float d0 = (s0 > 0.0f) ? sqrtfast(s0) : 0.0f;
            float d1 = (s1 > 0.0f) ? sqrtfast(s1) : 0.0f;
            DSMH[ip * 256 + jl] = __floats2half2_rn(d0, d1);
        }
    }
    if (tid < 256) {
        float m = mask[b * NN + tid];
        MSMH[tid] = __floats2half2_rn(m, m);
    }
    if (tid < 16) MROW[tid] = mask[row0 + tid];
    if (tid < 32) {
        float c = 0.0f;
#pragma unroll
        for (int m = 0; m < 8; m++) c += mask[b * NN + tid * 8 + m];
#pragma unroll
        for (int o = 16; o; o >>= 1) c += __shfl_xor_sync(0xffffffffu, c, o);
        if (tid == 0) *CNT = c;
    }
    __syncthreads();

    // ---------------- main edge loop (fp16-native, R13 form) ----------------
    {
        int jh = tid >> 8;
        int ip = (tid >> 5) & 7;
        int k0 = (tid & 31) * 4;

        __half2 wd2h[4], base2h[4];
        ull acc2[4];
#pragma unroll
        for (int d = 0; d < 4; d++) {
            float w = 0.5f * We1[2 * HH * HH + k0 + d];
            wd2h[d] = __floats2half2_rn(w, w);
            base2h[d] = __floats2half2_rn(BSM[(2 * ip) * HH + k0 + d],
                                          BSM[(2 * ip + 1) * HH + k0 + d]);
            acc2[d] = 0ULL;
        }
        const __half2* drow  = &DSMH[ip * 256 + jh * 128];
        const __half2* msrc  = &MSMH[jh * 128];
        const uint*    qbase = &QSMh[jh * 128 * HH + k0];

#pragma unroll 1
        for (int jt = 0; jt < 128; jt += 8) {
            __half2 macc[4];
#pragma unroll
            for (int d = 0; d < 4; d++) macc[d] = __floats2half2_rn(0.0f, 0.0f);
#pragma unroll
            for (int u = 0; u < 8; u++) {
                int jl = jt + u;
                __half2 d2 = drow[jl];
                __half2 m2 = msrc[jl];
                uint4 qr = *(const uint4*)&qbase[jl * HH];
                __half2 qh[4] = {u2h2(qr.x), u2h2(qr.y), u2h2(qr.z), u2h2(qr.w)};
#pragma unroll
                for (int d = 0; d < 4; d++) {
                    __half2 hf = __hfma2(d2, wd2h[d], __hadd2(base2h[d], qh[d]));
                    __half2 t2 = tanh2h(hf);
                    __half2 s2 = __hfma2(hf, t2, hf);
                    macc[d] = __hfma2(m2, s2, macc[d]);
                }
            }
#pragma unroll
            for (int d = 0; d < 4; d++) {
                float2 f = __half22float2(macc[d]);
                acc2[d] = add2(acc2[d], pack2(f.x, f.y));
            }
        }
#pragma unroll
        for (int d = 0; d < 4; d++)
            S2[jh * (HH * 8) + (k0 + d) * 8 + ip] = acc2[d];
    }
    __syncthreads();   // edge done; QSM region dead -> XA2/SU2/WC become live

    // post-edge: write X into XA2 alias, prefetch Wn2, merge S halves
    {
#pragma unroll
        for (int t = 0; t < 2; t++) {
            int idx = tid + t * 512;
            int e = idx & 127, p = idx >> 7;
            XA2[e * 8 + p] = pack2(xv[2 * t], xv[2 * t + 1]);
        }
        uint wc_s = smem_u32(WC) + tid * 16;
        const char* wsrc = (const char*)Wn2 + tid * 16;
#pragma unroll
        for (int i = 0; i < 8; i++)
            cp_async16(wc_s + i * 8192, wsrc + i * 8192);
        CP_COMMIT();                              // group G1
#pragma unroll
        for (int t = 0; t < 2; t++) {
            int i = tid + t * 512;
            S2[i] = add2(S2[i], S2[HH * 8 + i]);
        }
    }
    CP_WAIT(1);        // We2 (G0) complete; Wn2 (G1) may still be in flight
    __syncthreads();

    // ---------------- tail ----------------
    int k = tid & 127;
    int g = tid >> 7;
    float cnt = *CNT;

    // Stage A: agg from smem-resident We2 (LDS, no global latency)
    {
        ull acc2[2] = {0ULL, 0ULL};
        const float* Ws = WA + k;
#pragma unroll 16
        for (int e = 0; e < HH; e++) {
            float w = Ws[e * HH];
            ull w2 = pack2(w, w);
            acc2[0] = fma2(S2[e * 8 + 2 * g], w2, acc2[0]);
            acc2[1] = fma2(S2[e * 8 + 2 * g + 1], w2, acc2[1]);
        }
        float be2k = be2[k];
#pragma unroll
        for (int pp = 0; pp < 2; pp++) {
            int pr = 2 * g + pp;
            float lo, hi; unpack2(acc2[pp], lo, hi);
            float m0 = MROW[2 * pr], m1 = MROW[2 * pr + 1];
            float a0 = m0 * (lo + cnt * be2k) / fmaxf(m0 * cnt, 1.0f);
            float a1 = m1 * (hi + cnt * be2k) / fmaxf(m1 * cnt, 1.0f);
            XA2[(HH + k) * 8 + pr] = pack2(a0, a1);
        }
    }
    __syncthreads();

    // Stage B: u1 = silu([X|A] @ Wn1 + bn1)  (register-LDG path, R12 form)
    {
        float b1 = bn1[k];
        ull acc2[2] = {pack2(b1, b1), pack2(b1, b1)};
        const float* W = Wn1 + k;
        float w0[16], w1[16];
        loadw16(w0, W, 0);
#pragma unroll
        for (int c = 0; c < 16; c += 2) {
            loadw16(w1, W, c + 1);
            gemv_chunk(w0, XA2, c, g, acc2);
            if (c + 2 < 16) loadw16(w0, W, c + 2);
            gemv_chunk(w1, XA2, c + 1, g, acc2);
        }
#pragma unroll
        for (int pp = 0; pp < 2; pp++) {
            int pr = 2 * g + pp;
            float lo, hi; unpack2(acc2[pp], lo, hi);
            SU2[k * 8 + pr] = pack2(lo * fast_sigmoid(lo), hi * fast_sigmoid(hi));
        }
    }
    CP_WAIT(0);        // Wn2 resident (finished long ago, behind stages A+B)
    __syncthreads();

    // Stage C: out = node + m * (u1 @ Wn2 + bn2)  (smem-resident Wn2)
    {
        float b2 = bn2[k];
        ull acc2[2] = {pack2(b2, b2), pack2(b2, b2)};
        const float* Ws = WC + k;
#pragma unroll 16
        for (int e = 0; e < HH; e++) {
            float w = Ws[e * HH];
            ull w2 = pack2(w, w);
            acc2[0] = fma2(SU2[e * 8 + 2 * g], w2, acc2[0]);
            acc2[1] = fma2(SU2[e * 8 + 2 * g + 1], w2, acc2[1]);
        }
#pragma unroll
        for (int pp = 0; pp < 2; pp++) {
            int pr = 2 * g + pp;
            float lo, hi; unpack2(acc2[pp], lo, hi);
            float x0, x1; unpack2(XA2[k * 8 + pr], x0, x1);
            out[(row0 + 2 * pr) * HH + k] = x0 + MROW[2 * pr] * lo;
            out[(row0 + 2 * pr + 1) * HH + k] = x1 + MROW[2 * pr + 1] * hi;
        }
    }
}

extern "C" void kernel_launch(void* const* d_in, const int* in_sizes, int n_in,
                              void* d_out, int out_size) {
    (void)in_sizes; (void)n_in; (void)out_size;
    const float* node = (const float*)d_in[0];
    const float* pos  = (const float*)d_in[1];
    const float* mask = (const float*)d_in[2];
    const float* We1  = (const float*)d_in[3];
    const float* be1  = (const float*)d_in[4];
    const float* We2  = (const float*)d_in[5];
    const float* be2  = (const float*)d_in[6];
    const float* Wn1  = (const float*)d_in[7];
    const float* bn1  = (const float*)d_in[8];
    const float* Wn2  = (const float*)d_in[9];
    const float* bn2  = (const float*)d_in[10];
    float* out = (float*)d_out;

    cudaFuncSetAttribute(k_pq, cudaFuncAttributeMaxDynamicSharedMemorySize, PQ_SMEM);
    cudaFuncSetAttribute(k_fused, cudaFuncAttributeMaxDynamicSharedMemorySize, FU_SMEM);

    k_pq<<<ROWS / 16, 512, PQ_SMEM>>>(node, We1, be1);
    k_fused<<<dim3(NN / TIF, BB), 512, FU_SMEM>>>(node, pos, mask, We1, We2, be2,
                                                  Wn1, bn1, Wn2, bn2, out);
}

// round 15
// speedup vs baseline: 1.0007x; 1.0007x over previous
#include <cuda_runtime.h>
#include <cuda_bf16.h>
#include <cuda_fp16.h>

// Problem constants (B=8, N=256, H=128)
#define BB 8
#define NN 256
#define HH 128
#define ROWS (BB * NN)        // 2048
#define TIF 4                 // i-rows per fused CTA -> 512 CTAs, 2/SM, pipelined

typedef unsigned long long ull;
typedef unsigned int uint;

// Scratch: g_P = 0.5*(node@We1a + be1) f32 ; g_Qh = 0.5*(node@We1b) plain half
__device__ float  g_P[ROWS * HH];
__device__ __half g_Qh[ROWS * HH];

// ---------------- packed f32x2 / fp16 helpers ----------------
__device__ __forceinline__ ull fma2(ull a, ull b, ull c) {
    ull d; asm("fma.rn.f32x2 %0, %1, %2, %3;" : "=l"(d) : "l"(a), "l"(b), "l"(c)); return d;
}
__device__ __forceinline__ ull add2(ull a, ull b) {
    ull d; asm("add.rn.f32x2 %0, %1, %2;" : "=l"(d) : "l"(a), "l"(b)); return d;
}
__device__ __forceinline__ ull mul2(ull a, ull b) {
    ull d; asm("mul.rn.f32x2 %0, %1, %2;" : "=l"(d) : "l"(a), "l"(b)); return d;
}
__device__ __forceinline__ ull pack2(float lo, float hi) {
    ull d; asm("mov.b64 %0, {%1, %2};" : "=l"(d) : "f"(lo), "f"(hi)); return d;
}
__device__ __forceinline__ void unpack2(ull v, float& lo, float& hi) {
    asm("mov.b64 {%0, %1}, %2;" : "=f"(lo), "=f"(hi) : "l"(v));
}
__device__ __forceinline__ float sqrtfast(float x) {
    float y; asm("sqrt.approx.f32 %0, %1;" : "=f"(y) : "f"(x)); return y;
}
__device__ __forceinline__ float fast_sigmoid(float x) {
    float e; asm("ex2.approx.f32 %0, %1;" : "=f"(e) : "f"(-1.4426950408889634f * x));
    float r; asm("rcp.approx.f32 %0, %1;" : "=f"(r) : "f"(1.0f + e));
    return r;
}
__device__ __forceinline__ __half2 tanh2h(__half2 h) {
    unsigned u = *reinterpret_cast<unsigned*>(&h);
    asm("tanh.approx.f16x2 %0, %0;" : "+r"(u));
    return *reinterpret_cast<__half2*>(&u);
}
__device__ __forceinline__ __half2 u2h2(uint u) { return *reinterpret_cast<__half2*>(&u); }
__device__ __forceinline__ uint h2u(__half2 h) { return *reinterpret_cast<uint*>(&h); }

// ---------------------------------------------------------------------------
// Kernel 1: P' = 0.5*(node@We1a + be1) f32 ; Q' = 0.5*(node@We1b) plain half
// grid 128 x 512 thr, 16 rows/CTA; full We1 staged in smem (unchanged core).
// ---------------------------------------------------------------------------
#define PQ_SMEM (131072 + 8192)
__global__ __launch_bounds__(512, 1)
void k_pq(const float* __restrict__ node,
          const float* __restrict__ We1,
          const float* __restrict__ be1) {
    extern __shared__ __align__(16) char smem_pq[];
    float* wsm = (float*)smem_pq;
    ull*   xs2 = (ull*)(smem_pq + 131072);

    int row0 = blockIdx.x * 16;
    int tid = threadIdx.x;
    int k = tid & 127;
    int half = (tid >> 7) & 1;
    int rg = tid >> 8;

    {
        const float4* wsrc = (const float4*)We1;
        float4* wdst = (float4*)wsm;
#pragma unroll
        for (int i = 0; i < 16; i++) wdst[tid + i * 512] = wsrc[tid + i * 512];
    }
    {
#pragma unroll
        for (int t = 0; t < 2; t++) {
            int idx = tid + t * 512;
            int e = idx & 127, p = idx >> 7;
            xs2[e * 8 + p] = pack2(node[(row0 + 2 * p) * HH + e],
                                   node[(row0 + 2 * p + 1) * HH + e]);
        }
    }
    __syncthreads();

    const float* W = wsm + half * (HH * HH) + k;
    float bv = half ? 0.0f : be1[k];
    ull acc2[4];
#pragma unroll
    for (int p = 0; p < 4; p++) acc2[p] = pack2(bv, bv);

#pragma unroll 8
    for (int e = 0; e < HH; e++) {
        float w = W[e * HH];
        ull w2 = pack2(w, w);
        ulonglong2 xa = *(const ulonglong2*)&xs2[e * 8 + rg * 4];
        ulonglong2 xb = *(const ulonglong2*)&xs2[e * 8 + rg * 4 + 2];
        acc2[0] = fma2(xa.x, w2, acc2[0]);
        acc2[1] = fma2(xa.y, w2, acc2[1]);
        acc2[2] = fma2(xb.x, w2, acc2[2]);
        acc2[3] = fma2(xb.y, w2, acc2[3]);
    }

    ull hc = pack2(0.5f, 0.5f);
    if (half == 0) {
#pragma unroll
        for (int p = 0; p < 4; p++) {
            float lo, hi; unpack2(mul2(acc2[p], hc), lo, hi);
            int pr = rg * 4 + p;
            g_P[(row0 + 2 * pr) * HH + k] = lo;
            g_P[(row0 + 2 * pr + 1) * HH + k] = hi;
        }
    } else {
#pragma unroll
        for (int p = 0; p < 4; p++) {
            float lo, hi; unpack2(mul2(acc2[p], hc), lo, hi);
            int pr = rg * 4 + p;
            g_Qh[(row0 + 2 * pr) * HH + k] = __float2half(lo);
            g_Qh[(row0 + 2 * pr + 1) * HH + k] = __float2half(hi);
        }
    }
}

// ---------------------------------------------------------------------------
// Fused kernel, TIF=4: grid (64,8)=512 CTAs, 256 threads, 2 CTAs/SM.
// Edge: thread = (k-group kg<16 [8 k], row ii<4, j-quarter jq<4 [64 j]).
//   fp16 silu: HFMA2(dist_dup, wd, HADD2(base, q)) -> tanh.f16x2 -> 2xHFMA2.
//   Q plain half (k-pairs), dist/mask duplicated half2.
// S: per-thread k-pair f32 accum -> Sf[jq][ii][k] -> repack to row-pair S2p.
// Tail: thread = (k<128, pair g<2); register double-buffered weights.
// ---------------------------------------------------------------------------
#define QSM_OFF  0          // __half[256][128]            65536
#define BSM_OFF  65536      // float[4][128]               2048
#define DSM_OFF  67584      // __half2[4][256] dup         4096
#define MSM_OFF  71680      // __half2[256] dup            1024
#define SF_OFF   72704      // float[4][4][128]            8192
#define S2P_OFF  80896      // ull[128][2]                 2048
#define XA2_OFF  82944      // ull[256][2]                 4096
#define SU2_OFF  87040      // ull[128][2]                 2048
#define MROW_OFF 89088      // float[4]
#define CNT_OFF  89120      // float
#define FU_SMEM  89152

__global__ __launch_bounds__(256, 2)
void k_fused(const float* __restrict__ node,
             const float* __restrict__ pos,
             const float* __restrict__ mask,
             const float* __restrict__ We1,
             const float* __restrict__ We2,
             const float* __restrict__ be2,
             const float* __restrict__ Wn1,
             const float* __restrict__ bn1,
             const float* __restrict__ Wn2,
             const float* __restrict__ bn2,
             float* __restrict__ out) {
    extern __shared__ __align__(16) char smem[];
    __half*  QSMh = (__half*)(smem + QSM_OFF);
    float*   BSM  = (float*)(smem + BSM_OFF);
    __half2* DSMH = (__half2*)(smem + DSM_OFF);
    __half2* MSMH = (__half2*)(smem + MSM_OFF);
    float*   Sf   = (float*)(smem + SF_OFF);     // [(jq*4+ii)*128 + k]
    ull*     S2p  = (ull*)(smem + S2P_OFF);      // [e*2 + g] = (S_2g, S_2g+1)
    ull*     XA2  = (ull*)(smem + XA2_OFF);      // [e*2 + g]
    ull*     SU2  = (ull*)(smem + SU2_OFF);
    float*   MROW = (float*)(smem + MROW_OFF);
    float*   CNT  = (float*)(smem + CNT_OFF);

    int i0 = blockIdx.x * TIF;
    int b  = blockIdx.y;
    int tid = threadIdx.x;
    int row0 = b * NN + i0;

    // ---------------- prologue ----------------
    {   // Q (whole batch, 64 KB) + P rows
        const float4* qsrc = (const float4*)&g_Qh[b * NN * HH];
#pragma unroll
        for (int i = 0; i < 16; i++)
            ((float4*)QSMh)[tid + i * 256] = qsrc[tid + i * 256];
        if (tid < 128)
            ((float4*)BSM)[tid] = ((const float4*)&g_P[row0 * HH])[tid];
    }
    {   // X row-pairs into XA2[e*2+p]
#pragma unroll
        for (int t = 0; t < 2; t++) {
            int idx = tid + t * 256;
            int e = idx >> 1, p = idx & 1;
            XA2[e * 2 + p] = pack2(node[(row0 + 2 * p) * HH + e],
                                   node[(row0 + 2 * p + 1) * HH + e]);
        }
    }
    {   // dist tile 4 rows x 256 j, duplicated fp16
#pragma unroll
        for (int t = 0; t < 4; t++) {
            int idx = tid + t * 256;
            int r = idx >> 8, jl = idx & 255;
            const float* pi = &pos[(row0 + r) * 3];
            const float* pj = &pos[(b * NN + jl) * 3];
            float dx = pi[0] - pj[0], dy = pi[1] - pj[1], dz = pi[2] - pj[2];
            float sq = fmaf(dx, dx, fmaf(dy, dy, dz * dz));
            float d = (sq > 0.0f) ? sqrtfast(sq) : 0.0f;
            DSMH[r * 256 + jl] = __floats2half2_rn(d, d);
        }
    }
    {
        float m = mask[b * NN + tid];
        MSMH[tid] = __floats2half2_rn(m, m);
    }
    if (tid < 4) MROW[tid] = mask[row0 + tid];
    if (tid < 32) {
        float c = 0.0f;
#pragma unroll
        for (int m = 0; m < 8; m++) c += mask[b * NN + tid * 8 + m];
#pragma unroll
        for (int o = 16; o; o >>= 1) c += __shfl_xor_sync(0xffffffffu, c, o);
        if (tid == 0) *CNT = c;
    }
    __syncthreads();

    // ---------------- main edge loop ----------------
    {
        int kg = tid & 15;                // 8 k values: k0..k0+7
        int ii = (tid >> 4) & 3;          // row
        int jq = tid >> 6;                // j quarter (64 j)
        int k0 = kg * 8;

        __half2 wd2h[4], base2h[4];
        ull acc2[4] = {0ULL, 0ULL, 0ULL, 0ULL};
#pragma unroll
        for (int d = 0; d < 4; d++) {
            wd2h[d] = __floats2half2_rn(0.5f * We1[2 * HH * HH + k0 + 2 * d],
                                        0.5f * We1[2 * HH * HH + k0 + 2 * d + 1]);
            base2h[d] = __floats2half2_rn(BSM[ii * HH + k0 + 2 * d],
                                          BSM[ii * HH + k0 + 2 * d + 1]);
        }
        const __half2* drow  = &DSMH[ii * 256 + jq * 64];
        const __half2* msrc  = &MSMH[jq * 64];
        const __half*  qbase = &QSMh[(jq * 64) * HH + k0];

#pragma unroll 1
        for (int jt = 0; jt < 64; jt += 8) {
            __half2 macc[4];
#pragma unroll
            for (int d = 0; d < 4; d++) macc[d] = __floats2half2_rn(0.0f, 0.0f);
#pragma unroll
            for (int u = 0; u < 8; u++) {
                int jl = jt + u;
                __half2 d2 = drow[jl];
                __half2 m2 = msrc[jl];
                uint4 qr = *(const uint4*)(qbase + jl * HH);
                __half2 qh[4] = {u2h2(qr.x), u2h2(qr.y), u2h2(qr.z), u2h2(qr.w)};
#pragma unroll
                for (int d = 0; d < 4; d++) {
                    __half2 hf = __hfma2(d2, wd2h[d], __hadd2(base2h[d], qh[d])); // h/2
                    __half2 t2 = tanh2h(hf);
                    __half2 s2 = __hfma2(hf, t2, hf);      // silu(h)
                    macc[d] = __hfma2(m2, s2, macc[d]);    // += m * silu
                }
            }
#pragma unroll
            for (int d = 0; d < 4; d++) {
                float2 f = __half22float2(macc[d]);
                acc2[d] = add2(acc2[d], pack2(f.x, f.y));
            }
        }
        // store S (k-contiguous floats per row)
        float* sdst = &Sf[(jq * 4 + ii) * HH + k0];
        float a0l, a0h, a1l, a1h;
        unpack2(acc2[0], a0l, a0h); unpack2(acc2[1], a1l, a1h);
        *(float4*)sdst = make_float4(a0l, a0h, a1l, a1h);
        unpack2(acc2[2], a0l, a0h); unpack2(acc2[3], a1l, a1h);
        *(float4*)(sdst + 4) = make_float4(a0l, a0h, a1l, a1h);
    }
    __syncthreads();

    // repack S: merge 4 j-quarters, transpose to row-pair packing
    {
        int e = tid >> 1, rp = tid & 1;
        float lo = 0.0f, hi = 0.0f;
#pragma unroll
        for (int jq = 0; jq < 4; jq++) {
            lo += Sf[(jq * 4 + 2 * rp) * HH + e];
            hi += Sf[(jq * 4 + 2 * rp + 1) * HH + e];
        }
        S2p[e * 2 + rp] = pack2(lo, hi);
    }
    __syncthreads();

    // ---------------- tail: 3 GEMV stages (1 row-pair per thread) ----------------
    int k = tid & 127;
    int g = tid >> 7;                     // pair g -> rows 2g, 2g+1
    float cnt = *CNT;

    // Stage A: agg = m*(S@We2 + cnt*be2)/max(m*cnt,1) -> XA2[(HH+k)*2+g]
    {
        ull acc = 0ULL;
        const float* W = We2 + k;
        float w0[16], w1[16];
#pragma unroll
        for (int e = 0; e < 16; e++) w0[e] = W[e * HH];
#pragma unroll
        for (int c = 0; c < 8; c++) {
            float* wc = (c & 1) ? w1 : w0;
            float* wn = (c & 1) ? w0 : w1;
            if (c < 7) {
#pragma unroll
                for (int e = 0; e < 16; e++) wn[e] = W[((c + 1) * 16 + e) * HH];
            }
#pragma unroll
            for (int e = 0; e < 16; e++)
                acc = fma2(S2p[(c * 16 + e) * 2 + g], pack2(wc[e], wc[e]), acc);
        }
        float be2k = be2[k];
        float lo, hi; unpack2(acc, lo, hi);
        float m0 = MROW[2 * g], m1 = MROW[2 * g + 1];
        float a0 = m0 * (lo + cnt * be2k) / fmaxf(m0 * cnt, 1.0f);
        float a1 = m1 * (hi + cnt * be2k) / fmaxf(m1 * cnt, 1.0f);
        XA2[(HH + k) * 2 + g] = pack2(a0, a1);
    }
    __syncthreads();

    // Stage B: u1 = silu([X|A] @ Wn1 + bn1) -> SU2
    {
        float b1 = bn1[k];
        ull acc = pack2(b1, b1);
        const float* W = Wn1 + k;
        float w0[16], w1[16];
#pragma unroll
        for (int e = 0; e < 16; e++) w0[e] = W[e * HH];
#pragma unroll
        for (int c = 0; c < 16; c++) {
            float* wc = (c & 1) ? w1 : w0;
            float* wn = (c & 1) ? w0 : w1;
            if (c < 15) {
#pragma unroll
                for (int e = 0; e < 16; e++) wn[e] = W[((c + 1) * 16 + e) * HH];
            }
#pragma unroll
            for (int e = 0; e < 16; e++)
                acc = fma2(XA2[(c * 16 + e) * 2 + g], pack2(wc[e], wc[e]), acc);
        }
        float lo, hi; unpack2(acc, lo, hi);
        SU2[k * 2 + g] = pack2(lo * fast_sigmoid(lo), hi * fast_sigmoid(hi));
    }
    __syncthreads();

    // Stage C: out = node + m * (u1 @ Wn2 + bn2)
    {
        float b2 = bn2[k];
        ull acc = pack2(b2, b2);
        const float* W = Wn2 + k;
        float w0[16], w1[16];
#pragma unroll
        for (int e = 0; e < 16; e++) w0[e] = W[e * HH];
#pragma unroll
        for (int c = 0; c < 8; c++) {
            float* wc = (c & 1) ? w1 : w0;
            float* wn = (c & 1) ? w0 : w1;
            if (c < 7) {
#pragma unroll
                for (int e = 0; e < 16; e++) wn[e] = W[((c + 1) * 16 + e) * HH];
            }
#pragma unroll
            for (int e = 0; e < 16; e++)
                acc = fma2(SU2[(c * 16 + e) * 2 + g], pack2(wc[e], wc[e]), acc);
        }
        float lo, hi; unpack2(acc, lo, hi);
        float x0, x1; unpack2(XA2[k * 2 + g], x0, x1);
        out[(row0 + 2 * g) * HH + k] = x0 + MROW[2 * g] * lo;
        out[(row0 + 2 * g + 1) * HH + k] = x1 + MROW[2 * g + 1] * hi;
    }
}

extern "C" void kernel_launch(void* const* d_in, const int* in_sizes, int n_in,
                              void* d_out, int out_size) {
    (void)in_sizes; (void)n_in; (void)out_size;
    const float* node = (const float*)d_in[0];
    const float* pos  = (const float*)d_in[1];
    const float* mask = (const float*)d_in[2];
    const float* We1  = (const float*)d_in[3];
    const float* be1  = (const float*)d_in[4];
    const float* We2  = (const float*)d_in[5];
    const float* be2  = (const float*)d_in[6];
    const float* Wn1  = (const float*)d_in[7];
    const float* bn1  = (const float*)d_in[8];
    const float* Wn2  = (const float*)d_in[9];
    const float* bn2  = (const float*)d_in[10];
    float* out = (float*)d_out;

    cudaFuncSetAttribute(k_pq, cudaFuncAttributeMaxDynamicSharedMemorySize, PQ_SMEM);
    cudaFuncSetAttribute(k_fused, cudaFuncAttributeMaxDynamicSharedMemorySize, FU_SMEM);

    k_pq<<<ROWS / 16, 512, PQ_SMEM>>>(node, We1, be1);
    k_fused<<<dim3(NN / TIF, BB), 256, FU_SMEM>>>(node, pos, mask, We1, We2, be2,
                                                  Wn1, bn1, Wn2, bn2, out);
}

// round 17
// speedup vs baseline: 1.0457x; 1.0450x over previous
#include <cuda_runtime.h>
#include <cuda_bf16.h>
#include <cuda_fp16.h>

// Problem constants (B=8, N=256, H=128)
#define BB 8
#define NN 256
#define HH 128
#define ROWS (BB * NN)        // 2048
#define TIF 16                // i-rows per fused CTA

typedef unsigned long long ull;
typedef unsigned int uint;

// Scratch: g_P = 0.5*(node@We1a + be1) f32 ; g_Qh = 0.5*(node@We1b) dup half2
__device__ float g_P[ROWS * HH];
__device__ uint  g_Qh[ROWS * HH];

// ---------------- packed f32x2 / fp16 helpers ----------------
__device__ __forceinline__ ull fma2(ull a, ull b, ull c) {
    ull d; asm("fma.rn.f32x2 %0, %1, %2, %3;" : "=l"(d) : "l"(a), "l"(b), "l"(c)); return d;
}
__device__ __forceinline__ ull add2(ull a, ull b) {
    ull d; asm("add.rn.f32x2 %0, %1, %2;" : "=l"(d) : "l"(a), "l"(b)); return d;
}
__device__ __forceinline__ ull mul2(ull a, ull b) {
    ull d; asm("mul.rn.f32x2 %0, %1, %2;" : "=l"(d) : "l"(a), "l"(b)); return d;
}
__device__ __forceinline__ ull pack2(float lo, float hi) {
    ull d; asm("mov.b64 %0, {%1, %2};" : "=l"(d) : "f"(lo), "f"(hi)); return d;
}
__device__ __forceinline__ void unpack2(ull v, float& lo, float& hi) {
    asm("mov.b64 {%0, %1}, %2;" : "=f"(lo), "=f"(hi) : "l"(v));
}
__device__ __forceinline__ float sqrtfast(float x) {
    float y; asm("sqrt.approx.f32 %0, %1;" : "=f"(y) : "f"(x)); return y;
}
__device__ __forceinline__ float fast_sigmoid(float x) {
    float e; asm("ex2.approx.f32 %0, %1;" : "=f"(e) : "f"(-1.4426950408889634f * x));
    float r; asm("rcp.approx.f32 %0, %1;" : "=f"(r) : "f"(1.0f + e));
    return r;
}
__device__ __forceinline__ __half2 tanh2h(__half2 h) {
    unsigned u = *reinterpret_cast<unsigned*>(&h);
    asm("tanh.approx.f16x2 %0, %0;" : "+r"(u));
    return *reinterpret_cast<__half2*>(&u);
}
__device__ __forceinline__ __half2 u2h2(uint u) { return *reinterpret_cast<__half2*>(&u); }
__device__ __forceinline__ uint h2u(__half2 h) { return *reinterpret_cast<uint*>(&h); }

// ---- tail GEMV helpers: [pair][e] layout, ulonglong2 operand reads ----
__device__ __forceinline__ void loadw16(float (&buf)[16], const float* Wk, int c) {
#pragma unroll
    for (int e = 0; e < 16; e++) buf[e] = Wk[(c * 16 + e) * HH];
}
// one 16-e chunk over two pair-rows; 2 LDS.128 + 4 fma2 per 2 e
__device__ __forceinline__ void gemv2(const float (&w)[16], const ull* rA,
                                      const ull* rB, int c, ull (&acc)[2]) {
#pragma unroll
    for (int eo = 0; eo < 8; eo++) {
        int e = c * 16 + eo * 2;
        ulonglong2 sa = *(const ulonglong2*)&rA[e];
        ulonglong2 sb = *(const ulonglong2*)&rB[e];
        ull wlo = pack2(w[eo * 2], w[eo * 2]);
        ull whi = pack2(w[eo * 2 + 1], w[eo * 2 + 1]);
        acc[0] = fma2(sa.x, wlo, acc[0]);
        acc[0] = fma2(sa.y, whi, acc[0]);
        acc[1] = fma2(sb.x, wlo, acc[1]);
        acc[1] = fma2(sb.y, whi, acc[1]);
    }
}

// ---------------------------------------------------------------------------
// Kernel 1 (R13 form): P' f32, Q' dup-half2. Full We1 staged in smem.
// ---------------------------------------------------------------------------
#define PQ_SMEM (131072 + 8192)
__global__ __launch_bounds__(512, 1)
void k_pq(const float* __restrict__ node,
          const float* __restrict__ We1,
          const float* __restrict__ be1) {
    extern __shared__ __align__(16) char smem_pq[];
    float* wsm = (float*)smem_pq;
    ull*   xs2 = (ull*)(smem_pq + 131072);

    int row0 = blockIdx.x * 16;
    int tid = threadIdx.x;
    int k = tid & 127;
    int half = (tid >> 7) & 1;
    int rg = tid >> 8;

    {
        const float4* wsrc = (const float4*)We1;
        float4* wdst = (float4*)wsm;
#pragma unroll
        for (int i = 0; i < 16; i++) wdst[tid + i * 512] = wsrc[tid + i * 512];
    }
    {
#pragma unroll
        for (int t = 0; t < 2; t++) {
            int idx = tid + t * 512;
            int e = idx & 127, p = idx >> 7;
            xs2[e * 8 + p] = pack2(node[(row0 + 2 * p) * HH + e],
                                   node[(row0 + 2 * p + 1) * HH + e]);
        }
    }
    __syncthreads();

    const float* W = wsm + half * (HH * HH) + k;
    float bv = half ? 0.0f : be1[k];
    ull acc2[4];
#pragma unroll
    for (int p = 0; p < 4; p++) acc2[p] = pack2(bv, bv);

#pragma unroll 8
    for (int e = 0; e < HH; e++) {
        float w = W[e * HH];
        ull w2 = pack2(w, w);
        ulonglong2 xa = *(const ulonglong2*)&xs2[e * 8 + rg * 4];
        ulonglong2 xb = *(const ulonglong2*)&xs2[e * 8 + rg * 4 + 2];
        acc2[0] = fma2(xa.x, w2, acc2[0]);
        acc2[1] = fma2(xa.y, w2, acc2[1]);
        acc2[2] = fma2(xb.x, w2, acc2[2]);
        acc2[3] = fma2(xb.y, w2, acc2[3]);
    }

    ull hc = pack2(0.5f, 0.5f);
    if (half == 0) {
#pragma unroll
        for (int p = 0; p < 4; p++) {
            float lo, hi; unpack2(mul2(acc2[p], hc), lo, hi);
            int pr = rg * 4 + p;
            g_P[(row0 + 2 * pr) * HH + k] = lo;
            g_P[(row0 + 2 * pr + 1) * HH + k] = hi;
        }
    } else {
#pragma unroll
        for (int p = 0; p < 4; p++) {
            float lo, hi; unpack2(mul2(acc2[p], hc), lo, hi);
            int pr = rg * 4 + p;
            g_Qh[(row0 + 2 * pr) * HH + k] = h2u(__floats2half2_rn(lo, lo));
            g_Qh[(row0 + 2 * pr + 1) * HH + k] = h2u(__floats2half2_rn(hi, hi));
        }
    }
}

// ---------------------------------------------------------------------------
// Fused kernel: R13 edge + [pair][e]-layout tail (half the operand LDS count).
// grid (N/TIF, B) = 128 CTAs, 512 threads.
// ---------------------------------------------------------------------------
#define QSM_OFF  0          // uint[256][128] dup-half2   131072
#define BSM_OFF  131072     // float[16][128]             8192
#define DSM_OFF  139264     // __half2[8][256]            8192
#define MSM_OFF  147456     // __half2[256]               1024
#define S2_OFF   148480     // ull[2][8][128]  [jh][ip][e] 16384
#define XAP_OFF  164864     // ull[8][256]     [pr][e]     16384
#define SUP_OFF  181248     // ull[8][128]     [pr][e]     8192
#define MROW_OFF 189440     // float[16]
#define CNT_OFF  189504     // float
#define FU_SMEM  189568

__global__ __launch_bounds__(512, 1)
void k_fused(const float* __restrict__ node,
             const float* __restrict__ pos,
             const float* __restrict__ mask,
             const float* __restrict__ We1,
             const float* __restrict__ We2,
             const float* __restrict__ be2,
             const float* __restrict__ Wn1,
             const float* __restrict__ bn1,
             const float* __restrict__ Wn2,
             const float* __restrict__ bn2,
             float* __restrict__ out) {
    extern __shared__ __align__(16) char smem[];
    uint*    QSMh = (uint*)(smem + QSM_OFF);
    float*   BSM  = (float*)(smem + BSM_OFF);
    __half2* DSMH = (__half2*)(smem + DSM_OFF);
    __half2* MSMH = (__half2*)(smem + MSM_OFF);
    ull*     S2   = (ull*)(smem + S2_OFF);      // [jh][ip][e]
    ull*     XAp  = (ull*)(smem + XAP_OFF);     // [pr][e], e<256
    ull*     SUp  = (ull*)(smem + SUP_OFF);     // [pr][e], e<128
    float*   MROW = (float*)(smem + MROW_OFF);
    float*   CNT  = (float*)(smem + CNT_OFF);

    int i0 = blockIdx.x * TIF;
    int b  = blockIdx.y;
    int tid = threadIdx.x;
    int row0 = b * NN + i0;

    // ---------------- prologue ----------------
    {
        const float4* qsrc = (const float4*)&g_Qh[b * NN * HH];
#pragma unroll
        for (int i = 0; i < 16; i++)
            ((float4*)QSMh)[tid + i * 512] = qsrc[tid + i * 512];
        const float4* bsrc = (const float4*)&g_P[row0 * HH];
        ((float4*)BSM)[tid] = bsrc[tid];
    }
    {   // X row-pairs into XAp[p][e]
#pragma unroll
        for (int t = 0; t < 2; t++) {
            int idx = tid + t * 512;
            int e = idx & 127, p = idx >> 7;
            XAp[p * 256 + e] = pack2(node[(row0 + 2 * p) * HH + e],
                                     node[(row0 + 2 * p + 1) * HH + e]);
        }
    }
    {   // dist row-pair tile: 8 ip x 256 j, fp16
#pragma unroll
        for (int t = 0; t < 4; t++) {
            int idx = tid + t * 512;
            int ip = idx >> 8, jl = idx & 255;
            const float* p0 = &pos[(row0 + 2 * ip) * 3];
            const float* p1 = &pos[(row0 + 2 * ip + 1) * 3];
            const float* pj = &pos[(b * NN + jl) * 3];
            float jx = pj[0], jy = pj[1], jz = pj[2];
            float dx0 = p0[0] - jx, dy0 = p0[1] - jy, dz0 = p0[2] - jz;
            float dx1 = p1[0] - jx, dy1 = p1[1] - jy, dz1 = p1[2] - jz;
            float s0 = fmaf(dx0, dx0, fmaf(dy0, dy0, dz0 * dz0));
            float s1 = fmaf(dx1, dx1, fmaf(dy1, dy1, dz1 * dz1));
            float d0 = (s0 > 0.0f) ? sqrtfast(s0) : 0.0f;
            float d1 = (s1 > 0.0f) ? sqrtfast(s1) : 0.0f;
            DSMH[ip * 256 + jl] = __floats2half2_rn(d0, d1);
        }
    }
    if (tid < 256) {
        float m = mask[b * NN + tid];
        MSMH[tid] = __floats2half2_rn(m, m);
    }
    if (tid < 16) MROW[tid] = mask[row0 + tid];
    if (tid < 32) {
        float c = 0.0f;
#pragma unroll
        for (int m = 0; m < 8; m++) c += mask[b * NN + tid * 8 + m];
#pragma unroll
        for (int o = 16; o; o >>= 1) c += __shfl_xor_sync(0xffffffffu, c, o);
        if (tid == 0) *CNT = c;
    }
    __syncthreads();

    // ---------------- main edge loop (fp16-native, R13 form) ----------------
    {
        int jh = tid >> 8;
        int ip = (tid >> 5) & 7;
        int k0 = (tid & 31) * 4;

        __half2 wd2h[4], base2h[4];
        ull acc2[4] = {0ULL, 0ULL, 0ULL, 0ULL};
#pragma unroll
        for (int d = 0; d < 4; d++) {
            float w = 0.5f * We1[2 * HH * HH + k0 + d];
            wd2h[d] = __floats2half2_rn(w, w);
            base2h[d] = __floats2half2_rn(BSM[(2 * ip) * HH + k0 + d],
                                          BSM[(2 * ip + 1) * HH + k0 + d]);
        }
        const __half2* drow  = &DSMH[ip * 256 + jh * 128];
        const __half2* msrc  = &MSMH[jh * 128];
        const uint*    qbase = &QSMh[jh * 128 * HH + k0];

#pragma unroll 1
        for (int jt = 0; jt < 128; jt += 8) {
            __half2 macc[4];
#pragma unroll
            for (int d = 0; d < 4; d++) macc[d] = __floats2half2_rn(0.0f, 0.0f);
#pragma unroll
            for (int u = 0; u < 8; u++) {
                int jl = jt + u;
                __half2 d2 = drow[jl];
                __half2 m2 = msrc[jl];
                uint4 qr = *(const uint4*)(qbase + jl * HH);
                __half2 qh[4] = {u2h2(qr.x), u2h2(qr.y), u2h2(qr.z), u2h2(qr.w)};
#pragma unroll
                for (int d = 0; d < 4; d++) {
                    __half2 hf = __hfma2(d2, wd2h[d], __hadd2(base2h[d], qh[d]));
                    __half2 t2 = tanh2h(hf);
                    __half2 s2 = __hfma2(hf, t2, hf);
                    macc[d] = __hfma2(m2, s2, macc[d]);
                }
            }
#pragma unroll
            for (int d = 0; d < 4; d++) {
                float2 f = __half22float2(macc[d]);
                acc2[d] = add2(acc2[d], pack2(f.x, f.y));
            }
        }
        // [jh][ip][e] layout: 4 consecutive ull per thread
        ull* sdst = &S2[(jh * 8 + ip) * HH + k0];
#pragma unroll
        for (int d = 0; d < 4; d++) sdst[d] = acc2[d];
    }
    __syncthreads();

    // merge the two j-half S buffers in place -> S2[0][ip][e]
    {
#pragma unroll
        for (int t = 0; t < 2; t++) {
            int i = tid + t * 512;
            S2[i] = add2(S2[i], S2[1024 + i]);
        }
    }
    __syncthreads();

    // ---------------- tail: 3 GEMV stages ----------------
    int k = tid & 127;
    int g = tid >> 7;                     // pair group: pairs 2g, 2g+1
    float cnt = *CNT;
    const ull* rSA = &S2[(2 * g) * HH];
    const ull* rSB = &S2[(2 * g + 1) * HH];

    // Stage A: agg -> XAp[pr][HH+k]
    {
        ull acc2[2] = {0ULL, 0ULL};
        const float* W = We2 + k;
        float w0[16], w1[16];
        loadw16(w0, W, 0);
#pragma unroll
        for (int c = 0; c < 8; c += 2) {
            loadw16(w1, W, c + 1);
            gemv2(w0, rSA, rSB, c, acc2);
            if (c + 2 < 8) loadw16(w0, W, c + 2);
            gemv2(w1, rSA, rSB, c + 1, acc2);
        }
        float be2k = be2[k];
#pragma unroll
        for (int pp = 0; pp < 2; pp++) {
            int pr = 2 * g + pp;
            float lo, hi; unpack2(acc2[pp], lo, hi);
            float m0 = MROW[2 * pr], m1 = MROW[2 * pr + 1];
            float a0 = m0 * (lo + cnt * be2k) / fmaxf(m0 * cnt, 1.0f);
            float a1 = m1 * (hi + cnt * be2k) / fmaxf(m1 * cnt, 1.0f);
            XAp[pr * 256 + HH + k] = pack2(a0, a1);
        }
    }
    __syncthreads();

    // Stage B: u1 = silu([X|A] @ Wn1 + bn1) -> SUp
    {
        float b1 = bn1[k];
        ull acc2[2] = {pack2(b1, b1), pack2(b1, b1)};
        const float* W = Wn1 + k;
        const ull* rXA = &XAp[(2 * g) * 256];
        const ull* rXB = &XAp[(2 * g + 1) * 256];
        float w0[16], w1[16];
        loadw16(w0, W, 0);
#pragma unroll
        for (int c = 0; c < 16; c += 2) {
            loadw16(w1, W, c + 1);
            gemv2(w0, rXA, rXB, c, acc2);
            if (c + 2 < 16) loadw16(w0, W, c + 2);
            gemv2(w1, rXA, rXB, c + 1, acc2);
        }
#pragma unroll
        for (int pp = 0; pp < 2; pp++) {
            int pr = 2 * g + pp;
            float lo, hi; unpack2(acc2[pp], lo, hi);
            SUp[pr * HH + k] = pack2(lo * fast_sigmoid(lo), hi * fast_sigmoid(hi));
        }
    }
    __syncthreads();

    // Stage C: out = node + m * (u1 @ Wn2 + bn2)
    {
        float b2 = bn2[k];
        ull acc2[2] = {pack2(b2, b2), pack2(b2, b2)};
        const float* W = Wn2 + k;
        const ull* rUA = &SUp[(2 * g) * HH];
        const ull* rUB = &SUp[(2 * g + 1) * HH];
        float w0[16], w1[16];
        loadw16(w0, W, 0);
#pragma unroll
        for (int c = 0; c < 8; c += 2) {
            loadw16(w1, W, c + 1);
            gemv2(w0, rUA, rUB, c, acc2);
            if (c + 2 < 8) loadw16(w0, W, c + 2);
            gemv2(w1, rUA, rUB, c + 1, acc2);
        }
#pragma unroll
        for (int pp = 0; pp < 2; pp++) {
            int pr = 2 * g + pp;
            float lo, hi; unpack2(acc2[pp], lo, hi);
            float x0, x1; unpack2(XAp[pr * 256 + k], x0, x1);
            out[(row0 + 2 * pr) * HH + k] = x0 + MROW[2 * pr] * lo;
            out[(row0 + 2 * pr + 1) * HH + k] = x1 + MROW[2 * pr + 1] * hi;
        }
    }
}

extern "C" void kernel_launch(void* const* d_in, const int* in_sizes, int n_in,
                              void* d_out, int out_size) {
    (void)in_sizes; (void)n_in; (void)out_size;
    const float* node = (const float*)d_in[0];
    const float* pos  = (const float*)d_in[1];
    const float* mask = (const float*)d_in[2];
    const float* We1  = (const float*)d_in[3];
    const float* be1  = (const float*)d_in[4];
    const float* We2  = (const float*)d_in[5];
    const float* be2  = (const float*)d_in[6];
    const float* Wn1  = (const float*)d_in[7];
    const float* bn1  = (const float*)d_in[8];
    const float* Wn2  = (const float*)d_in[9];
    const float* bn2  = (const float*)d_in[10];
    float* out = (float*)d_out;

    cudaFuncSetAttribute(k_pq, cudaFuncAttributeMaxDynamicSharedMemorySize, PQ_SMEM);
    cudaFuncSetAttribute(k_fused, cudaFuncAttributeMaxDynamicSharedMemorySize, FU_SMEM);

    k_pq<<<ROWS / 16, 512, PQ_SMEM>>>(node, We1, be1);
    k_fused<<<dim3(NN / TIF, BB), 512, FU_SMEM>>>(node, pos, mask, We1, We2, be2,
                                                  Wn1, bn1, Wn2, bn2, out);
}